// round 1
// baseline (speedup 1.0000x reference)
#include <cuda_runtime.h>
#include <cstdint>

// Problem shape (fixed by the dataset):
//   x:      [4, 2048, 4096] f32  -> A [M=8192, K=4096] row-major
//   weight: [4096, 4096]    f32  -> W [N=4096, K=4096] row-major
//   bias:   [4096]          f32
//   sw:     [262144]        f32
//   idx:    [2, 262144]     i32  (rows then cols)
//   out:    [4, 2048, 4096] f32  = A @ W'^T + bias,  W' = W + scatter(sw)

#define M_DIM 8192
#define N_DIM 4096
#define K_DIM 4096

// Dense W' scratch (device global array: allocation-free per harness rules)
__device__ float g_wt[(size_t)N_DIM * K_DIM];

// ---------------------------------------------------------------------------
// Kernel 1: copy weight -> scratch (vectorized)
// ---------------------------------------------------------------------------
__global__ void copy_weight_kernel(const float4* __restrict__ w) {
    size_t idx = (size_t)blockIdx.x * blockDim.x + threadIdx.x;
    reinterpret_cast<float4*>(g_wt)[idx] = w[idx];
}

// ---------------------------------------------------------------------------
// Kernel 2: COO scatter-add (SCALING = 1.0)
// ---------------------------------------------------------------------------
__global__ void scatter_add_kernel(const float* __restrict__ sw,
                                   const int* __restrict__ rows,
                                   const int* __restrict__ cols,
                                   int nnz) {
    int i = blockIdx.x * blockDim.x + threadIdx.x;
    if (i < nnz) {
        atomicAdd(&g_wt[(size_t)rows[i] * K_DIM + cols[i]], sw[i]);
    }
}

// ---------------------------------------------------------------------------
// Kernel 3: SGEMM  C[M,N] = A[M,K] * W'[N,K]^T + bias
//   128x128 block tile, BK=16, 256 threads, 8x8 per-thread microtile,
//   double-buffered shared memory, 1 __syncthreads per k-tile.
// ---------------------------------------------------------------------------
#define BM 128
#define BN 128
#define BK 16
#define PAD 4
#define LDS_A (BM + PAD)   // 132 floats/row: keeps float4 alignment, reduces STS conflicts
#define NT (K_DIM / BK)    // 256 k-tiles

__global__ __launch_bounds__(256, 2)
void sgemm_kernel(const float* __restrict__ A,
                  const float* __restrict__ bias,
                  float* __restrict__ C) {
    __shared__ float As[2][BK][LDS_A];
    __shared__ float Bs[2][BK][LDS_A];

    const float* __restrict__ B = g_wt;

    const int bm  = blockIdx.y * BM;
    const int bn  = blockIdx.x * BN;
    const int tid = threadIdx.x;
    const int tx  = tid & 15;    // 0..15 -> N direction
    const int ty  = tid >> 4;    // 0..15 -> M direction

    // Global-load mapping: 512 float4 per tile per matrix, 2 per thread.
    // idx -> row m = idx/4 (0..127), k-subchunk kk = (idx%4)*4.
    float4 pa[2], pb[2];

    const float* Abase = A + (size_t)bm * K_DIM;
    const float* Bbase = B + (size_t)bn * K_DIM;

#define LDG_TILE(dst, base, t)                                              \
    {                                                                       \
        _Pragma("unroll")                                                   \
        for (int i = 0; i < 2; i++) {                                       \
            int idx = tid + i * 256;                                        \
            int m   = idx >> 2;                                             \
            int kk  = (idx & 3) << 2;                                       \
            dst[i] = *reinterpret_cast<const float4*>(                      \
                (base) + (size_t)m * K_DIM + (t) * BK + kk);                \
        }                                                                   \
    }

#define STS_TILE(smem, src, buf)                                            \
    {                                                                       \
        _Pragma("unroll")                                                   \
        for (int i = 0; i < 2; i++) {                                       \
            int idx = tid + i * 256;                                        \
            int m   = idx >> 2;                                             \
            int kk  = (idx & 3) << 2;                                       \
            smem[buf][kk + 0][m] = src[i].x;                                \
            smem[buf][kk + 1][m] = src[i].y;                                \
            smem[buf][kk + 2][m] = src[i].z;                                \
            smem[buf][kk + 3][m] = src[i].w;                                \
        }                                                                   \
    }

    // Prologue: tile 0 into buffer 0
    LDG_TILE(pa, Abase, 0);
    LDG_TILE(pb, Bbase, 0);
    STS_TILE(As, pa, 0);
    STS_TILE(Bs, pb, 0);
    __syncthreads();

    float acc[8][8];
#pragma unroll
    for (int i = 0; i < 8; i++)
#pragma unroll
        for (int j = 0; j < 8; j++) acc[i][j] = 0.0f;

    int buf = 0;
    for (int t = 0; t < NT; t++) {
        if (t + 1 < NT) {
            LDG_TILE(pa, Abase, t + 1);
            LDG_TILE(pb, Bbase, t + 1);
        }

#pragma unroll
        for (int kk = 0; kk < BK; kk++) {
            float ar[8], br[8];
            *reinterpret_cast<float4*>(&ar[0]) =
                *reinterpret_cast<const float4*>(&As[buf][kk][ty * 8 + 0]);
            *reinterpret_cast<float4*>(&ar[4]) =
                *reinterpret_cast<const float4*>(&As[buf][kk][ty * 8 + 4]);
            *reinterpret_cast<float4*>(&br[0]) =
                *reinterpret_cast<const float4*>(&Bs[buf][kk][tx * 8 + 0]);
            *reinterpret_cast<float4*>(&br[4]) =
                *reinterpret_cast<const float4*>(&Bs[buf][kk][tx * 8 + 4]);
#pragma unroll
            for (int i = 0; i < 8; i++)
#pragma unroll
                for (int j = 0; j < 8; j++)
                    acc[i][j] = fmaf(ar[i], br[j], acc[i][j]);
        }

        if (t + 1 < NT) {
            STS_TILE(As, pa, buf ^ 1);
            STS_TILE(Bs, pb, buf ^ 1);
            __syncthreads();
            buf ^= 1;
        }
    }

    // Epilogue: add bias, vectorized stores
    float bv[8];
    *reinterpret_cast<float4*>(&bv[0]) =
        *reinterpret_cast<const float4*>(&bias[bn + tx * 8 + 0]);
    *reinterpret_cast<float4*>(&bv[4]) =
        *reinterpret_cast<const float4*>(&bias[bn + tx * 8 + 4]);

#pragma unroll
    for (int i = 0; i < 8; i++) {
        int m = bm + ty * 8 + i;
        float4 v0, v1;
        v0.x = acc[i][0] + bv[0];
        v0.y = acc[i][1] + bv[1];
        v0.z = acc[i][2] + bv[2];
        v0.w = acc[i][3] + bv[3];
        v1.x = acc[i][4] + bv[4];
        v1.y = acc[i][5] + bv[5];
        v1.z = acc[i][6] + bv[6];
        v1.w = acc[i][7] + bv[7];
        *reinterpret_cast<float4*>(&C[(size_t)m * N_DIM + bn + tx * 8 + 0]) = v0;
        *reinterpret_cast<float4*>(&C[(size_t)m * N_DIM + bn + tx * 8 + 4]) = v1;
    }
}

// ---------------------------------------------------------------------------
// Launch
// ---------------------------------------------------------------------------
extern "C" void kernel_launch(void* const* d_in, const int* in_sizes, int n_in,
                              void* d_out, int out_size) {
    const float* x    = (const float*)d_in[0];   // [8192, 4096]
    const float* w    = (const float*)d_in[1];   // [4096, 4096]
    const float* bias = (const float*)d_in[2];   // [4096]
    const float* sw   = (const float*)d_in[3];   // [nnz]
    const int*   idx  = (const int*)d_in[4];     // [2, nnz]
    float*       out  = (float*)d_out;

    const int nnz = in_sizes[3];                 // 262144

    // 1) W' = W
    {
        const int total_f4 = (N_DIM * K_DIM) / 4; // 4194304
        copy_weight_kernel<<<total_f4 / 256, 256>>>(
            reinterpret_cast<const float4*>(w));
    }

    // 2) W' += scatter(sw)
    {
        const int* rows = idx;
        const int* cols = idx + nnz;
        scatter_add_kernel<<<(nnz + 255) / 256, 256>>>(sw, rows, cols, nnz);
    }

    // 3) out = x @ W'^T + bias
    {
        dim3 grid(N_DIM / BN, M_DIM / BM);  // (32, 64)
        sgemm_kernel<<<grid, 256>>>(x, bias, out);
    }
}

// round 3
// speedup vs baseline: 3.9675x; 3.9675x over previous
#include <cuda_runtime.h>
#include <cstdint>

// Problem shape (fixed):
//   x:      [8192, 4096] f32 (A, row-major)      d_in[0]
//   weight: [4096, 4096] f32 (W, row-major)      d_in[1]
//   bias:   [4096] f32                           d_in[2]
//   sw:     [262144] f32                         d_in[3]
//   idx:    [2, 262144] i32 (rows, cols)         d_in[4]
//   out = x @ (W + scatter)^T + bias   [8192, 4096] f32
//
// NOTE: this toolchain lowers through a plain compute_103 PTX target, so
// tcgen05/TMEM are unavailable. We use arch-portable mma.sync tf32 instead.

#define M_DIM 8192
#define N_DIM 4096
#define K_DIM 4096

#define BM 128
#define BN 256
#define BK 32
#define STAGES 4
#define NKT (K_DIM / BK)        // 128

#define A_STAGE_BYTES (BM * BK * 4)     // 16384
#define B_STAGE_BYTES (BN * BK * 4)     // 32768
#define SMEM_TOTAL (STAGES * (A_STAGE_BYTES + B_STAGE_BYTES))   // 196608

// Device scratch: W' = round_tf32(W + scatter)
__device__ float g_wt[(size_t)N_DIM * K_DIM];

// ---------------------------------------------------------------------------
// helpers
// ---------------------------------------------------------------------------
__device__ __forceinline__ uint32_t smem_u32(const void* p) {
    uint32_t a;
    asm("{ .reg .u64 t; cvta.to.shared.u64 t, %1; cvt.u32.u64 %0, t; }"
        : "=r"(a) : "l"(p));
    return a;
}

__device__ __forceinline__ uint32_t f2tf32(float f) {
    uint32_t u;
    asm("cvt.rna.tf32.f32 %0, %1;" : "=r"(u) : "f"(f));
    return u;
}

#define CP_ASYNC16(dst, src) \
    asm volatile("cp.async.cg.shared.global [%0], [%1], 16;" :: "r"(dst), "l"(src))
#define CP_COMMIT() asm volatile("cp.async.commit_group;" ::: "memory")
#define CP_WAIT2()  asm volatile("cp.async.wait_group 2;" ::: "memory")

__device__ __forceinline__ void mma_tf32(float& c0, float& c1, float& c2, float& c3,
                                         uint32_t a0, uint32_t a1, uint32_t a2, uint32_t a3,
                                         uint32_t b0, uint32_t b1) {
    asm volatile(
        "mma.sync.aligned.m16n8k8.row.col.f32.tf32.tf32.f32 "
        "{%0,%1,%2,%3}, {%4,%5,%6,%7}, {%8,%9}, {%0,%1,%2,%3};"
        : "+f"(c0), "+f"(c1), "+f"(c2), "+f"(c3)
        : "r"(a0), "r"(a1), "r"(a2), "r"(a3), "r"(b0), "r"(b1));
}

// ---------------------------------------------------------------------------
// Prologue kernels
// ---------------------------------------------------------------------------
__global__ void copy_w_kernel(const float4* __restrict__ w) {
    size_t i = (size_t)blockIdx.x * blockDim.x + threadIdx.x;
    reinterpret_cast<float4*>(g_wt)[i] = w[i];
}

__global__ void scatter_add_kernel(const float* __restrict__ sw,
                                   const int* __restrict__ rows,
                                   const int* __restrict__ cols, int nnz) {
    int i = blockIdx.x * blockDim.x + threadIdx.x;
    if (i < nnz)
        atomicAdd(&g_wt[(size_t)rows[i] * K_DIM + cols[i]], sw[i]);
}

__global__ void round_w_kernel() {
    size_t i = (size_t)blockIdx.x * blockDim.x + threadIdx.x;
    float4 v = reinterpret_cast<float4*>(g_wt)[i];
    v.x = __uint_as_float(f2tf32(v.x));
    v.y = __uint_as_float(f2tf32(v.y));
    v.z = __uint_as_float(f2tf32(v.z));
    v.w = __uint_as_float(f2tf32(v.w));
    reinterpret_cast<float4*>(g_wt)[i] = v;
}

// ---------------------------------------------------------------------------
// GEMM: C[M,N] = A @ W'^T + bias
//   mma.sync m16n8k8 tf32, CTA 128x256, warps 2x4 (64x64 each), BK=32,
//   4-stage cp.async pipeline, XOR-swizzled smem (conflict-free LDS.32).
// ---------------------------------------------------------------------------
__global__ __launch_bounds__(256, 1)
void gemm_mma_kernel(const float* __restrict__ A,
                     const float* __restrict__ bias,
                     float* __restrict__ C) {
    extern __shared__ char smem[];
    const uint32_t sb = smem_u32(smem);

    const int tid  = threadIdx.x;
    const int wid  = tid >> 5;
    const int lane = tid & 31;
    const int lq   = lane & 3;      // k within 4-chunk / col pair
    const int lr   = lane >> 2;     // 0..7 row-in-fragment

    const int warpM = (wid >> 2) * 64;   // 0 or 64
    const int warpN = (wid & 3) * 64;    // 0,64,128,192

    const int bm = blockIdx.y * BM;
    const int bn = blockIdx.x * BN;

    const float* Ab = A + (size_t)bm * K_DIM;
    const float* Bb = g_wt + (size_t)bn * K_DIM;

    // tile loaders: chunk (row, kc) -> smem row*128B + ((kc ^ (row&7))*16)
#define LOAD_TILE(t, s)                                                         \
    {                                                                           \
        const uint32_t ab = sb + (s) * A_STAGE_BYTES;                           \
        _Pragma("unroll")                                                       \
        for (int j = 0; j < 4; j++) {                                           \
            int i = tid + j * 256;              /* 0..1023 */                   \
            int r = i >> 3, kc = i & 7;                                         \
            uint32_t dst = ab + (uint32_t)(r * 128 + ((kc ^ (r & 7)) << 4));    \
            CP_ASYNC16(dst, Ab + (size_t)r * K_DIM + (t) * BK + kc * 4);        \
        }                                                                       \
        const uint32_t bb = sb + STAGES * A_STAGE_BYTES + (s) * B_STAGE_BYTES;  \
        _Pragma("unroll")                                                       \
        for (int j = 0; j < 8; j++) {                                           \
            int i = tid + j * 256;              /* 0..2047 */                   \
            int r = i >> 3, kc = i & 7;                                         \
            uint32_t dst = bb + (uint32_t)(r * 128 + ((kc ^ (r & 7)) << 4));    \
            CP_ASYNC16(dst, Bb + (size_t)r * K_DIM + (t) * BK + kc * 4);        \
        }                                                                       \
    }

    // prologue: tiles 0..2 into stages 0..2
#pragma unroll
    for (int p = 0; p < STAGES - 1; p++) {
        LOAD_TILE(p, p);
        CP_COMMIT();
    }

    float acc[4][8][4];
#pragma unroll
    for (int i = 0; i < 4; i++)
#pragma unroll
        for (int j = 0; j < 8; j++)
#pragma unroll
            for (int q = 0; q < 4; q++) acc[i][j][q] = 0.0f;

    for (int t = 0; t < NKT; t++) {
        const int s = t & (STAGES - 1);

        CP_WAIT2();          // tile t resident
        __syncthreads();     // all warps done with stage (t-1) reads

        // prefetch tile t+3 into stage (t+3)&3 (== stage (t-1)&3, now free)
        if (t + STAGES - 1 < NKT) {
            LOAD_TILE(t + STAGES - 1, (t + STAGES - 1) & (STAGES - 1));
        }
        CP_COMMIT();         // always commit (empty groups in tail keep count)

        const float* As = reinterpret_cast<const float*>(smem + s * A_STAGE_BYTES);
        const float* Bs = reinterpret_cast<const float*>(
            smem + STAGES * A_STAGE_BYTES + s * B_STAGE_BYTES);

#pragma unroll
        for (int kk = 0; kk < BK; kk += 8) {
            const int kc0 = kk >> 2;
            const int c0 = ((kc0 ^ lr) << 2) + lq;        // float offset in row
            const int c1 = (((kc0 + 1) ^ lr) << 2) + lq;

            // A fragments (rounded to tf32 in-register)
            uint32_t af[4][4];
#pragma unroll
            for (int mt = 0; mt < 4; mt++) {
                const int r0 = warpM + mt * 16 + lr;
                const int r1 = r0 + 8;
                af[mt][0] = f2tf32(As[(r0 << 5) + c0]);
                af[mt][1] = f2tf32(As[(r1 << 5) + c0]);
                af[mt][2] = f2tf32(As[(r0 << 5) + c1]);
                af[mt][3] = f2tf32(As[(r1 << 5) + c1]);
            }
            // B fragments (already tf32-rounded in g_wt)
            uint32_t bf[8][2];
#pragma unroll
            for (int nt = 0; nt < 8; nt++) {
                const int n = warpN + nt * 8 + lr;
                bf[nt][0] = __float_as_uint(Bs[(n << 5) + c0]);
                bf[nt][1] = __float_as_uint(Bs[(n << 5) + c1]);
            }
#pragma unroll
            for (int mt = 0; mt < 4; mt++)
#pragma unroll
                for (int nt = 0; nt < 8; nt++)
                    mma_tf32(acc[mt][nt][0], acc[mt][nt][1],
                             acc[mt][nt][2], acc[mt][nt][3],
                             af[mt][0], af[mt][1], af[mt][2], af[mt][3],
                             bf[nt][0], bf[nt][1]);
        }
    }

    // Epilogue: bias + store (float2 per fragment row)
#pragma unroll
    for (int nt = 0; nt < 8; nt++) {
        const int col = bn + warpN + nt * 8 + lq * 2;
        const float bv0 = bias[col];
        const float bv1 = bias[col + 1];
#pragma unroll
        for (int mt = 0; mt < 4; mt++) {
            const int r0 = bm + warpM + mt * 16 + lr;
            float2 v0, v1;
            v0.x = acc[mt][nt][0] + bv0;
            v0.y = acc[mt][nt][1] + bv1;
            v1.x = acc[mt][nt][2] + bv0;
            v1.y = acc[mt][nt][3] + bv1;
            *reinterpret_cast<float2*>(&C[(size_t)r0 * N_DIM + col]) = v0;
            *reinterpret_cast<float2*>(&C[(size_t)(r0 + 8) * N_DIM + col]) = v1;
        }
    }
}

// ---------------------------------------------------------------------------
// Launch
// ---------------------------------------------------------------------------
extern "C" void kernel_launch(void* const* d_in, const int* in_sizes, int n_in,
                              void* d_out, int out_size) {
    const float* x    = (const float*)d_in[0];
    const float* w    = (const float*)d_in[1];
    const float* bias = (const float*)d_in[2];
    const float* sw   = (const float*)d_in[3];
    const int*   idx  = (const int*)d_in[4];
    float*       out  = (float*)d_out;
    const int nnz = in_sizes[3];

    // 1) W' = W
    copy_w_kernel<<<(N_DIM * K_DIM / 4) / 256, 256>>>(
        reinterpret_cast<const float4*>(w));
    // 2) W' += scatter(sw)
    scatter_add_kernel<<<(nnz + 255) / 256, 256>>>(sw, idx, idx + nnz, nnz);
    // 3) W' = round_tf32(W')  (exact rounding after scatter)
    round_w_kernel<<<(N_DIM * K_DIM / 4) / 256, 256>>>();

    // 4) GEMM (A rounded to tf32 in-register inside the kernel)
    static int smem_set = 0;
    if (!smem_set) {
        cudaFuncSetAttribute(gemm_mma_kernel,
                             cudaFuncAttributeMaxDynamicSharedMemorySize, SMEM_TOTAL);
        smem_set = 1;
    }
    dim3 grid(N_DIM / BN, M_DIM / BM);   // (16, 64)
    gemm_mma_kernel<<<grid, 256, SMEM_TOTAL>>>(x, bias, out);
}

// round 4
// speedup vs baseline: 4.0951x; 1.0322x over previous
#include <cuda_runtime.h>
#include <cstdint>

// Problem shape (fixed):
//   x:      [8192, 4096] f32 (A, row-major)      d_in[0]
//   weight: [4096, 4096] f32 (W, row-major)      d_in[1]
//   bias:   [4096] f32                           d_in[2]
//   sw:     [262144] f32                         d_in[3]
//   idx:    [2, 262144] i32 (rows, cols)         d_in[4]
//   out = x @ (W + scatter)^T + bias   [8192, 4096] f32
//
// tcgen05 unavailable (toolchain lowers via plain compute_103 PTX target);
// using arch-portable mma.sync m16n8k8 tf32 on the tensor pipe.

#define M_DIM 8192
#define N_DIM 4096
#define K_DIM 4096

#define BM 128
#define BN 256
#define BK 32
#define STAGES 4
#define NKT (K_DIM / BK)        // 128

#define A_STAGE_BYTES (BM * BK * 4)     // 16384
#define B_STAGE_BYTES (BN * BK * 4)     // 32768
#define SMEM_TOTAL (STAGES * (A_STAGE_BYTES + B_STAGE_BYTES))   // 196608

// Device scratch: W' = round_tf32(W + scatter), x' = round_tf32(x)
__device__ float g_wt[(size_t)N_DIM * K_DIM];
__device__ float g_x[(size_t)M_DIM * K_DIM];

// ---------------------------------------------------------------------------
// helpers
// ---------------------------------------------------------------------------
__device__ __forceinline__ uint32_t smem_u32(const void* p) {
    uint32_t a;
    asm("{ .reg .u64 t; cvta.to.shared.u64 t, %1; cvt.u32.u64 %0, t; }"
        : "=r"(a) : "l"(p));
    return a;
}

__device__ __forceinline__ float round_tf32(float f) {
    uint32_t u;
    asm("cvt.rna.tf32.f32 %0, %1;" : "=r"(u) : "f"(f));
    return __uint_as_float(u);
}

#define CP_ASYNC16(dst, src) \
    asm volatile("cp.async.cg.shared.global [%0], [%1], 16;" :: "r"(dst), "l"(src))
#define CP_COMMIT() asm volatile("cp.async.commit_group;" ::: "memory")
#define CP_WAIT2()  asm volatile("cp.async.wait_group 2;" ::: "memory")

__device__ __forceinline__ void mma_tf32(float& c0, float& c1, float& c2, float& c3,
                                         uint32_t a0, uint32_t a1, uint32_t a2, uint32_t a3,
                                         uint32_t b0, uint32_t b1) {
    asm volatile(
        "mma.sync.aligned.m16n8k8.row.col.f32.tf32.tf32.f32 "
        "{%0,%1,%2,%3}, {%4,%5,%6,%7}, {%8,%9}, {%0,%1,%2,%3};"
        : "+f"(c0), "+f"(c1), "+f"(c2), "+f"(c3)
        : "r"(a0), "r"(a1), "r"(a2), "r"(a3), "r"(b0), "r"(b1));
}

// ---------------------------------------------------------------------------
// Prologue kernels
// ---------------------------------------------------------------------------
__global__ void copy_w_kernel(const float4* __restrict__ w) {
    size_t i = (size_t)blockIdx.x * blockDim.x + threadIdx.x;
    reinterpret_cast<float4*>(g_wt)[i] = w[i];
}

__global__ void scatter_add_kernel(const float* __restrict__ sw,
                                   const int* __restrict__ rows,
                                   const int* __restrict__ cols, int nnz) {
    int i = blockIdx.x * blockDim.x + threadIdx.x;
    if (i < nnz)
        atomicAdd(&g_wt[(size_t)rows[i] * K_DIM + cols[i]], sw[i]);
}

__global__ void round_w_kernel() {
    size_t i = (size_t)blockIdx.x * blockDim.x + threadIdx.x;
    float4 v = reinterpret_cast<float4*>(g_wt)[i];
    v.x = round_tf32(v.x); v.y = round_tf32(v.y);
    v.z = round_tf32(v.z); v.w = round_tf32(v.w);
    reinterpret_cast<float4*>(g_wt)[i] = v;
}

__global__ void round_x_kernel(const float4* __restrict__ x) {
    size_t i = (size_t)blockIdx.x * blockDim.x + threadIdx.x;
    float4 v = x[i];
    v.x = round_tf32(v.x); v.y = round_tf32(v.y);
    v.z = round_tf32(v.z); v.w = round_tf32(v.w);
    reinterpret_cast<float4*>(g_x)[i] = v;
}

// ---------------------------------------------------------------------------
// GEMM: C[M,N] = A @ W'^T + bias
//   mma.sync m16n8k8 tf32, CTA 128x256, warps 2x4 (64x64 each), BK=32,
//   4-stage cp.async pipeline, XOR-swizzled smem (conflict-free LDS.32),
//   double-buffered register fragments across kk-steps.
// ---------------------------------------------------------------------------
__global__ __launch_bounds__(256, 1)
void gemm_mma_kernel(const float* __restrict__ bias,
                     float* __restrict__ C) {
    extern __shared__ char smem[];
    const uint32_t sb = smem_u32(smem);

    const int tid  = threadIdx.x;
    const int wid  = tid >> 5;
    const int lane = tid & 31;
    const int lq   = lane & 3;      // k within 4-chunk
    const int lr   = lane >> 2;     // 0..7 row-in-fragment

    const int warpM = (wid >> 2) * 64;   // 0 or 64
    const int warpN = (wid & 3) * 64;    // 0,64,128,192

    const int bm = blockIdx.y * BM;
    const int bn = blockIdx.x * BN;

    const float* Ab = g_x + (size_t)bm * K_DIM;
    const float* Bb = g_wt + (size_t)bn * K_DIM;

    // tile loaders: chunk (row, kc) -> smem row*128B + ((kc ^ (row&7))*16)
#define LOAD_TILE(t, s)                                                         \
    {                                                                           \
        const uint32_t ab = sb + (s) * A_STAGE_BYTES;                           \
        _Pragma("unroll")                                                       \
        for (int j = 0; j < 4; j++) {                                           \
            int i = tid + j * 256;              /* 0..1023 */                   \
            int r = i >> 3, kc = i & 7;                                         \
            uint32_t dst = ab + (uint32_t)(r * 128 + ((kc ^ (r & 7)) << 4));    \
            CP_ASYNC16(dst, Ab + (size_t)r * K_DIM + (t) * BK + kc * 4);        \
        }                                                                       \
        const uint32_t bb = sb + STAGES * A_STAGE_BYTES + (s) * B_STAGE_BYTES;  \
        _Pragma("unroll")                                                       \
        for (int j = 0; j < 8; j++) {                                           \
            int i = tid + j * 256;              /* 0..2047 */                   \
            int r = i >> 3, kc = i & 7;                                         \
            uint32_t dst = bb + (uint32_t)(r * 128 + ((kc ^ (r & 7)) << 4));    \
            CP_ASYNC16(dst, Bb + (size_t)r * K_DIM + (t) * BK + kc * 4);        \
        }                                                                       \
    }

    // fragment loader for kk-step j (j = 0..3), A already tf32-rounded
#define LOAD_FRAGS(j, af, bf)                                                   \
    {                                                                           \
        const int c0 = (((2 * (j)) ^ lr) << 2) + lq;                            \
        const int c1 = (((2 * (j) + 1) ^ lr) << 2) + lq;                        \
        _Pragma("unroll")                                                       \
        for (int mt = 0; mt < 4; mt++) {                                        \
            const int r0 = warpM + mt * 16 + lr;                                \
            const int r1 = r0 + 8;                                              \
            (af)[mt * 4 + 0] = *(const uint32_t*)&As[(r0 << 5) + c0];           \
            (af)[mt * 4 + 1] = *(const uint32_t*)&As[(r1 << 5) + c0];           \
            (af)[mt * 4 + 2] = *(const uint32_t*)&As[(r0 << 5) + c1];           \
            (af)[mt * 4 + 3] = *(const uint32_t*)&As[(r1 << 5) + c1];           \
        }                                                                       \
        _Pragma("unroll")                                                       \
        for (int nt = 0; nt < 8; nt++) {                                        \
            const int n = warpN + nt * 8 + lr;                                  \
            (bf)[nt * 2 + 0] = *(const uint32_t*)&Bs[(n << 5) + c0];            \
            (bf)[nt * 2 + 1] = *(const uint32_t*)&Bs[(n << 5) + c1];            \
        }                                                                       \
    }

#define MMA_BURST(af, bf)                                                       \
    {                                                                           \
        _Pragma("unroll")                                                       \
        for (int mt = 0; mt < 4; mt++)                                          \
            _Pragma("unroll")                                                   \
            for (int nt = 0; nt < 8; nt++)                                      \
                mma_tf32(acc[mt][nt][0], acc[mt][nt][1],                        \
                         acc[mt][nt][2], acc[mt][nt][3],                        \
                         (af)[mt * 4 + 0], (af)[mt * 4 + 1],                    \
                         (af)[mt * 4 + 2], (af)[mt * 4 + 3],                    \
                         (bf)[nt * 2 + 0], (bf)[nt * 2 + 1]);                   \
    }

    // prologue: tiles 0..2 into stages 0..2
#pragma unroll
    for (int p = 0; p < STAGES - 1; p++) {
        LOAD_TILE(p, p);
        CP_COMMIT();
    }

    float acc[4][8][4];
#pragma unroll
    for (int i = 0; i < 4; i++)
#pragma unroll
        for (int j = 0; j < 8; j++)
#pragma unroll
            for (int q = 0; q < 4; q++) acc[i][j][q] = 0.0f;

    uint32_t afr[2][16], bfr[2][16];

    for (int t = 0; t < NKT; t++) {
        const int s = t & (STAGES - 1);

        CP_WAIT2();          // tile t resident
        __syncthreads();     // all warps done reading retiring stage

        // prefetch tile t+3 into the now-free stage
        if (t + STAGES - 1 < NKT) {
            LOAD_TILE(t + STAGES - 1, (t + STAGES - 1) & (STAGES - 1));
        }
        CP_COMMIT();         // always commit (empty groups in tail keep count)

        const float* As = reinterpret_cast<const float*>(smem + s * A_STAGE_BYTES);
        const float* Bs = reinterpret_cast<const float*>(
            smem + STAGES * A_STAGE_BYTES + s * B_STAGE_BYTES);

        // software-pipelined fragment loads across the 4 kk-steps
        LOAD_FRAGS(0, afr[0], bfr[0]);
        LOAD_FRAGS(1, afr[1], bfr[1]);
        MMA_BURST(afr[0], bfr[0]);
        LOAD_FRAGS(2, afr[0], bfr[0]);
        MMA_BURST(afr[1], bfr[1]);
        LOAD_FRAGS(3, afr[1], bfr[1]);
        MMA_BURST(afr[0], bfr[0]);
        MMA_BURST(afr[1], bfr[1]);
    }

    // Epilogue: bias + store (float2 per fragment row)
#pragma unroll
    for (int nt = 0; nt < 8; nt++) {
        const int col = bn + warpN + nt * 8 + lq * 2;
        const float bv0 = bias[col];
        const float bv1 = bias[col + 1];
#pragma unroll
        for (int mt = 0; mt < 4; mt++) {
            const int r0 = bm + warpM + mt * 16 + lr;
            float2 v0, v1;
            v0.x = acc[mt][nt][0] + bv0;
            v0.y = acc[mt][nt][1] + bv1;
            v1.x = acc[mt][nt][2] + bv0;
            v1.y = acc[mt][nt][3] + bv1;
            *reinterpret_cast<float2*>(&C[(size_t)r0 * N_DIM + col]) = v0;
            *reinterpret_cast<float2*>(&C[(size_t)(r0 + 8) * N_DIM + col]) = v1;
        }
    }
}

// ---------------------------------------------------------------------------
// Launch
// ---------------------------------------------------------------------------
extern "C" void kernel_launch(void* const* d_in, const int* in_sizes, int n_in,
                              void* d_out, int out_size) {
    const float* x    = (const float*)d_in[0];
    const float* w    = (const float*)d_in[1];
    const float* bias = (const float*)d_in[2];
    const float* sw   = (const float*)d_in[3];
    const int*   idx  = (const int*)d_in[4];
    float*       out  = (float*)d_out;
    const int nnz = in_sizes[3];

    // 1) W' = W
    copy_w_kernel<<<(N_DIM * K_DIM / 4) / 256, 256>>>(
        reinterpret_cast<const float4*>(w));
    // 2) W' += scatter(sw)
    scatter_add_kernel<<<(nnz + 255) / 256, 256>>>(sw, idx, idx + nnz, nnz);
    // 3) W' = round_tf32(W')  (exact rounding after scatter)
    round_w_kernel<<<(N_DIM * K_DIM / 4) / 256, 256>>>();
    // 4) x' = round_tf32(x)   (moves cvt out of the GEMM inner loop)
    round_x_kernel<<<((size_t)M_DIM * K_DIM / 4) / 256, 256>>>(
        reinterpret_cast<const float4*>(x));

    // 5) GEMM
    static int smem_set = 0;
    if (!smem_set) {
        cudaFuncSetAttribute(gemm_mma_kernel,
                             cudaFuncAttributeMaxDynamicSharedMemorySize, SMEM_TOTAL);
        smem_set = 1;
    }
    dim3 grid(N_DIM / BN, M_DIM / BM);   // (16, 64)
    gemm_mma_kernel<<<grid, 256, SMEM_TOTAL>>>(bias, out);
}